// round 6
// baseline (speedup 1.0000x reference)
#include <cuda_runtime.h>
#include <stdint.h>
#include <math.h>

// Problem constants
#define ND 4       // digits
#define NS 2048    // samples
#define NBATCH 512
#define ALPHA_C 0.1f
#define NTICK (NBATCH * (NS / 256))   // 4096 tickets, one per 256-sample chunk
#define PERSIST_CTAS 1184             // 148 SMs * 8

// Device scratch
__device__ int      g_n1sum[NBATCH * NS];
__device__ float    g_E[NBATCH][ND * 10];   // exp(-sp)
__device__ int      g_sd[NBATCH][ND];       // decimal digits of s[b]
__device__ int      g_sv[NBATCH];           // s[b]
__device__ unsigned g_ticket;

// ---------------------------------------------------------------------------
// Accurate float log (musl logf, ~1 ulp) — prep-kernel only; must match the
// reference's sp bit-for-bit.
// ---------------------------------------------------------------------------
__device__ __forceinline__ float alogf(float x) {
    uint32_t ix = __float_as_uint(x);
    ix += 0x3f800000u - 0x3f3504f3u;
    int k = (int)(ix >> 23) - 127;
    ix = (ix & 0x007fffffu) + 0x3f3504f3u;
    float xm = __uint_as_float(ix);
    float f = xm - 1.0f;
    float s = f / (2.0f + f);
    float z = s * s;
    float w = z * z;
    float t1 = w * (0.40000972152f + w * 0.24279078841f);
    float t2 = z * (0.66666662693f + w * 0.28498786688f);
    float R = t2 + t1;
    float hfsq = 0.5f * f * f;
    float dk = (float)k;
    return s * (hfsq + R) + dk * 9.0580006145e-06f - hfsq + f
           + dk * 0.69313812256f;
}

// ---------------------------------------------------------------------------
// Prep kernel: once per row b, compute E = exp(-sp) (sp exactly as the
// reference), digits of s, and reset the work-stealing ticket.
// ---------------------------------------------------------------------------
__global__ void __launch_bounds__(64)
prep_kernel(const float* __restrict__ n1_logits,
            const float* __restrict__ counters,
            const int*   __restrict__ s_arr) {
    const int b = blockIdx.x;
    const int t = threadIdx.x;
    if (t < ND * 10) {
        float spf = n1_logits[b * (ND * 10) + t] - ALPHA_C * alogf(counters[t]);
        g_E[b][t] = (float)exp(-(double)spf);
    }
    if (t == 0) {
        int sv = s_arr[b];
        g_sv[b] = sv;
        g_sd[b][0] = sv / 1000;
        g_sd[b][1] = (sv / 100) % 10;
        g_sd[b][2] = (sv / 10) % 10;
        g_sd[b][3] = sv % 10;
        if (b == 0) g_ticket = 0u;
    }
}

// ---------------------------------------------------------------------------
// One category evaluation: full 20-round threefry2x32 (c0 = 0, k1 folded into
// x1init by the caller), then u -> lg2(u)*E, packed as
// (float-bits & ~15) | category. All values <= -0.0, so uint-min == argmax
// with ties to lowest category (JAX first-max semantics).
// ---------------------------------------------------------------------------
__device__ __forceinline__ uint32_t cat_eval(uint32_t k0, uint32_t k1,
                                             uint32_t ks2, uint32_t x1i,
                                             float E, int cc) {
    uint32_t x0 = k0, x1 = x1i + (uint32_t)cc;
#define TF_RND(r) { x0 += x1; x1 = __funnelshift_l(x1, x1, (r)); x1 ^= x0; }
    TF_RND(13) TF_RND(15) TF_RND(26) TF_RND(6)
    x0 += k1;  x1 += ks2 + 1u;
    TF_RND(17) TF_RND(29) TF_RND(16) TF_RND(24)
    x0 += ks2; x1 += k0 + 2u;
    TF_RND(13) TF_RND(15) TF_RND(26) TF_RND(6)
    x0 += k0;  x1 += k1 + 3u;
    TF_RND(17) TF_RND(29) TF_RND(16) TF_RND(24)
    x0 += k1;  x1 += ks2 + 4u;
    TF_RND(13) TF_RND(15) TF_RND(26) TF_RND(6)
    x0 += ks2; x1 += k0 + 5u;
#undef TF_RND
    uint32_t bits = x0 ^ x1;
    float u = __uint_as_float(0x3f800000u + (bits >> 9)) - 1.0f;
    float lg;
    asm("lg2.approx.f32 %0, %1;" : "=f"(lg) : "f"(u));
    float v = lg * E;   // argmax lg2(u)*E; v <= -0.0
    return (__float_as_uint(v) & 0xFFFFFFF0u) | (uint32_t)cc;
}

// ---------------------------------------------------------------------------
// Persistent work-stealing sampler. Each ticket = (row b, chunk of 256
// samples). Fine tickets erase both wave quantization and the per-row
// digit-0 work variance. Operands are warp-uniform __ldg loads (L1
// broadcast); the only barrier is the one ticket-broadcast per iteration.
// ---------------------------------------------------------------------------
__global__ void __launch_bounds__(256)
sampler_kernel(float* __restrict__ out, uint4 ka, uint4 kb) {
    __shared__ unsigned stk[2];
    const int t = threadIdx.x;

    const uint32_t K[8] = {ka.x, ka.y, ka.z, ka.w, kb.x, kb.y, kb.z, kb.w};

    int it = 0;
    for (;; it++) {
        if (t == 0) stk[it & 1] = atomicAdd(&g_ticket, 1u);
        __syncthreads();
        const unsigned tk = stk[it & 1];
        if (tk >= (unsigned)NTICK) break;

        const int b = (int)(tk >> 3);
        const int sidx = ((int)(tk & 7u)) * 256 + t;
        const uint32_t base = (uint32_t)(b * NS + sidx) * 10u;
        const float* __restrict__ E0 = &g_E[b][0];
        const int*   __restrict__ SD = &g_sd[b][0];

        int samp[ND];

        // ---- digit 0: ticket-uniform bound, pair-unrolled loop c = 0..mx --
        {
            const int mx = __ldg(SD + 0);
            const uint32_t k0 = K[0], k1 = K[1];
            const uint32_t ks2 = 0x1BD11BDAu ^ k0 ^ k1;
            const uint32_t bk = base + k1;
            uint32_t run = 0xFFFFFFFFu;
            int c = 0;
            for (; c + 1 <= mx; c += 2) {
                uint32_t p0 = cat_eval(k0, k1, ks2, bk, __ldg(E0 + c), c);
                uint32_t p1 = cat_eval(k0, k1, ks2, bk, __ldg(E0 + c + 1), c + 1);
                run = min(run, min(p0, p1));
            }
            if (c <= mx) {
                uint32_t p0 = cat_eval(k0, k1, ks2, bk, __ldg(E0 + c), c);
                run = min(run, p0);
            }
            samp[0] = (int)(run & 15u);
        }
        int constraint = (samp[0] != __ldg(SD + 0));

        // ---- digits 1..3: branch-free, all 10 categories, dual argmax ----
#pragma unroll
        for (int i = 1; i < ND; i++) {
            const int mx = __ldg(SD + i);
            const uint32_t k0 = K[2 * i], k1 = K[2 * i + 1];
            const uint32_t ks2 = 0x1BD11BDAu ^ k0 ^ k1;
            const uint32_t bk = base + k1;
            const float* E = E0 + i * 10;
            uint32_t pa = 0xFFFFFFFFu;  // argmax over all categories
            uint32_t pcu = 0xFFFFFFFFu; // argmax over c <= mx
#pragma unroll
            for (int c = 0; c < 10; c++) {
                uint32_t p = cat_eval(k0, k1, ks2, bk, __ldg(E + c), c);
                pa = min(pa, p);
                if (c <= mx) pcu = min(pcu, p);
            }
            int sm = (int)((constraint ? pa : pcu) & 15u);
            samp[i] = sm;
            constraint |= (sm != mx);
        }

        const int n1 = samp[0] * 1000 + samp[1] * 100 + samp[2] * 10 + samp[3];
        const int n2 = __ldg(&g_sv[b]) - n1;   // in [0, 10000)

        const int lin = b * NS + sidx;
        g_n1sum[lin] = n1;

        // Output: n1_samples[B,S,D,1] | n2d[B,S,D,1] | weights[B,S]
        float4* out_n1 = (float4*)out;
        float4* out_n2 = (float4*)(out + (size_t)NBATCH * NS * ND);
        out_n1[lin] = make_float4((float)samp[0], (float)samp[1],
                                  (float)samp[2], (float)samp[3]);
        out_n2[lin] = make_float4((float)(n2 / 1000), (float)((n2 / 100) % 10),
                                  (float)((n2 / 10) % 10), (float)(n2 % 10));
    }
}

// ---------------------------------------------------------------------------
// Per-row histogram (10^4 bins in smem) + gather -> weights.
// ---------------------------------------------------------------------------
__global__ void __launch_bounds__(512)
hist_kernel(float* __restrict__ w) {
    __shared__ int h[10000];
    const int b = blockIdx.x;
    int4* h4 = (int4*)h;
    for (int i = threadIdx.x; i < 2500; i += 512)
        h4[i] = make_int4(0, 0, 0, 0);
    __syncthreads();
    int v[NS / 512];
#pragma unroll
    for (int j = 0; j < NS / 512; j++)
        v[j] = g_n1sum[b * NS + threadIdx.x + j * 512];
#pragma unroll
    for (int j = 0; j < NS / 512; j++)
        atomicAdd(&h[v[j]], 1);
    __syncthreads();
#pragma unroll
    for (int j = 0; j < NS / 512; j++)
        w[b * NS + threadIdx.x + j * 512] = (float)h[v[j]];
}

// ---------------------------------------------------------------------------
// Host: key derivation (threefry on CPU, deterministic, no device work)
// ---------------------------------------------------------------------------
static inline uint32_t h_rotl(uint32_t x, int r) {
    return (x << r) | (x >> (32 - r));
}
static void tf2x32_h(uint32_t k0, uint32_t k1, uint32_t c0, uint32_t c1,
                     uint32_t* o0, uint32_t* o1) {
    uint32_t ks2 = 0x1BD11BDAu ^ k0 ^ k1;
    uint32_t x0 = c0 + k0, x1 = c1 + k1;
#define TFH(r) { x0 += x1; x1 = h_rotl(x1, (r)); x1 ^= x0; }
    TFH(13) TFH(15) TFH(26) TFH(6)
    x0 += k1;  x1 += ks2 + 1u;
    TFH(17) TFH(29) TFH(16) TFH(24)
    x0 += ks2; x1 += k0 + 2u;
    TFH(13) TFH(15) TFH(26) TFH(6)
    x0 += k0;  x1 += k1 + 3u;
    TFH(17) TFH(29) TFH(16) TFH(24)
    x0 += k1;  x1 += ks2 + 4u;
    TFH(13) TFH(15) TFH(26) TFH(6)
    x0 += ks2; x1 += k0 + 5u;
#undef TFH
    *o0 = x0; *o1 = x1;
}

extern "C" void kernel_launch(void* const* d_in, const int* in_sizes, int n_in,
                              void* d_out, int out_size) {
    const float* n1_logits = (const float*)d_in[0];
    const float* counters  = (const float*)d_in[1];
    const int*   s_arr     = (const int*)d_in[2];
    float* out = (float*)d_out;

    // jax.random.key(42) -> (0, 42); 4x split (partitionable mode);
    // categorical uses the sub key.
    uint32_t kk0 = 0u, kk1 = 42u;
    uint32_t keys[8];
    for (int i = 0; i < ND; i++) {
        uint32_t nk0, nk1, sk0, sk1;
        tf2x32_h(kk0, kk1, 0u, 0u, &nk0, &nk1);
        tf2x32_h(kk0, kk1, 0u, 1u, &sk0, &sk1);
        keys[2 * i]     = sk0;
        keys[2 * i + 1] = sk1;
        kk0 = nk0; kk1 = nk1;
    }
    uint4 ka = make_uint4(keys[0], keys[1], keys[2], keys[3]);
    uint4 kb = make_uint4(keys[4], keys[5], keys[6], keys[7]);

    prep_kernel<<<NBATCH, 64>>>(n1_logits, counters, s_arr);
    sampler_kernel<<<PERSIST_CTAS, 256>>>(out, ka, kb);

    float* w = out + (size_t)2 * NBATCH * NS * ND;
    hist_kernel<<<NBATCH, 512>>>(w);
}

// round 7
// speedup vs baseline: 1.0570x; 1.0570x over previous
#include <cuda_runtime.h>
#include <stdint.h>
#include <math.h>

// Problem constants
#define ND 4       // digits
#define NS 2048    // samples
#define NBATCH 512
#define ALPHA_C 0.1f

// scratch: n1_summed per (b,s)
__device__ int g_n1sum[NBATCH * NS];

// ---------------------------------------------------------------------------
// Accurate float log (musl logf, ~1 ulp) — 40 lanes per CTA, matches the
// reference's counter penalty bit-for-bit.
// ---------------------------------------------------------------------------
__device__ __forceinline__ float alogf(float x) {
    uint32_t ix = __float_as_uint(x);
    ix += 0x3f800000u - 0x3f3504f3u;
    int k = (int)(ix >> 23) - 127;
    ix = (ix & 0x007fffffu) + 0x3f3504f3u;
    float xm = __uint_as_float(ix);
    float f = xm - 1.0f;
    float s = f / (2.0f + f);
    float z = s * s;
    float w = z * z;
    float t1 = w * (0.40000972152f + w * 0.24279078841f);
    float t2 = z * (0.66666662693f + w * 0.28498786688f);
    float R = t2 + t1;
    float hfsq = 0.5f * f * f;
    float dk = (float)k;
    return s * (hfsq + R) + dk * 9.0580006145e-06f - hfsq + f
           + dk * 0.69313812256f;
}

// ---------------------------------------------------------------------------
// One category evaluation: full 20-round threefry2x32 (c0 = 0, k1 folded into
// x1init by the caller), then u -> lg2(u)*E, packed as
// (float-bits & ~15) | category. All values <= -0.0, so uint-min == argmax
// with ties to lowest category (JAX first-max semantics).
//
// Mantissa construct uses + (not |): bit-identical (no carries possible) but
// IMAD-able, so it rides the fma pipe instead of the saturated alu pipe.
// ---------------------------------------------------------------------------
__device__ __forceinline__ uint32_t cat_eval(uint32_t k0, uint32_t k1,
                                             uint32_t ks2, uint32_t x1i,
                                             float E, int cc) {
    uint32_t x0 = k0, x1 = x1i + (uint32_t)cc;
#define TF_RND(r) { x0 += x1; x1 = __funnelshift_l(x1, x1, (r)); x1 ^= x0; }
    TF_RND(13) TF_RND(15) TF_RND(26) TF_RND(6)
    x0 += k1;  x1 += ks2 + 1u;
    TF_RND(17) TF_RND(29) TF_RND(16) TF_RND(24)
    x0 += ks2; x1 += k0 + 2u;
    TF_RND(13) TF_RND(15) TF_RND(26) TF_RND(6)
    x0 += k0;  x1 += k1 + 3u;
    TF_RND(17) TF_RND(29) TF_RND(16) TF_RND(24)
    x0 += k1;  x1 += ks2 + 4u;
    TF_RND(13) TF_RND(15) TF_RND(26) TF_RND(6)
    x0 += ks2; x1 += k0 + 5u;
#undef TF_RND
    uint32_t bits = x0 ^ x1;
    float u = __uint_as_float(0x3f800000u + (bits >> 9)) - 1.0f;
    float lg;
    asm("lg2.approx.f32 %0, %1;" : "=f"(lg) : "f"(u));
    float v = lg * E;   // argmax lg2(u)*E; v <= -0.0
    return (__float_as_uint(v) & 0xFFFFFFF0u) | (uint32_t)cc;
}

// ---------------------------------------------------------------------------
// Main sampler: one thread per (b, s).
// argmax_c (sp_c + gumbel_c) == argmax_c lg2(u_c) * exp(-sp_c)  (see R2/R3).
// E = exp(-sp) via MUFU.EX2 (ex2.approx of sp * -log2e): ~5e-8 relative
// error, 30x below the 4-bit packing truncation already applied to v, so the
// selection is unchanged at our measured flip floor.
//
// Digit 0: maxim is block-uniform -> runtime-bound loop, ciphers beyond mx
//          skipped, pair-unrolled for 2-way ILP on the latency chain.
// Digits 1-3: all 10 categories, fully unrolled (10 independent chains),
//          dual argmax (full range + c<=mx prefix), select by constraint.
// ---------------------------------------------------------------------------
__global__ void __launch_bounds__(256)
sampler_kernel(const float* __restrict__ n1_logits,   // [B, D, 10]
               const float* __restrict__ counters,    // [D, 10]
               const int*   __restrict__ s_arr,       // [B]
               float* __restrict__ out,
               uint4 ka, uint4 kb) {
    __shared__ float    sE[ND * 10];  // exp(-sp)
    __shared__ int      sd[ND];       // decimal digits of s[b]
    __shared__ int      ssv;
    __shared__ uint32_t sK[2 * ND];   // per-digit threefry keys

    const int b = blockIdx.y;
    const int t = threadIdx.x;

    if (t < ND * 10) {
        // sp computed in float EXACTLY like the reference
        float spf = n1_logits[b * (ND * 10) + t] - ALPHA_C * alogf(counters[t]);
        float e;
        float a = spf * -1.4426950408889634f;   // -sp * log2(e)
        asm("ex2.approx.f32 %0, %1;" : "=f"(e) : "f"(a));
        sE[t] = e;
    }
    if (t == 0) {
        int sv = s_arr[b];
        ssv = sv;
        sd[0] = sv / 1000;
        sd[1] = (sv / 100) % 10;
        sd[2] = (sv / 10) % 10;
        sd[3] = sv % 10;
        sK[0] = ka.x; sK[1] = ka.y; sK[2] = ka.z; sK[3] = ka.w;
        sK[4] = kb.x; sK[5] = kb.y; sK[6] = kb.z; sK[7] = kb.w;
    }
    __syncthreads();

    const int sidx = blockIdx.x * 256 + t;
    const uint32_t base = (uint32_t)(b * NS + sidx) * 10u;

    int samp[ND];

    // ---- digit 0: block-uniform bound, pair-unrolled loop c = 0..mx ----
    {
        const int mx = sd[0];
        const uint32_t k0 = sK[0], k1 = sK[1];
        const uint32_t ks2 = 0x1BD11BDAu ^ k0 ^ k1;
        const uint32_t bk = base + k1;
        uint32_t run = 0xFFFFFFFFu;
        int c = 0;
        for (; c + 1 <= mx; c += 2) {
            uint32_t p0 = cat_eval(k0, k1, ks2, bk, sE[c], c);
            uint32_t p1 = cat_eval(k0, k1, ks2, bk, sE[c + 1], c + 1);
            run = min(run, min(p0, p1));
        }
        if (c <= mx) {   // tail (always runs when mx is even, incl. mx=0)
            uint32_t p0 = cat_eval(k0, k1, ks2, bk, sE[c], c);
            run = min(run, p0);
        }
        samp[0] = (int)(run & 15u);
    }
    int constraint = (samp[0] != sd[0]);

    // ---- digits 1..3: branch-free, all 10 categories, dual argmax ----
#pragma unroll
    for (int i = 1; i < ND; i++) {
        const int mx = sd[i];
        const uint32_t k0 = sK[2 * i], k1 = sK[2 * i + 1];
        const uint32_t ks2 = 0x1BD11BDAu ^ k0 ^ k1;
        const uint32_t bk = base + k1;
        const float* E = sE + i * 10;
        uint32_t pa = 0xFFFFFFFFu;  // argmax over all categories
        uint32_t pcu = 0xFFFFFFFFu; // argmax over c <= mx
#pragma unroll
        for (int c = 0; c < 10; c++) {
            uint32_t p = cat_eval(k0, k1, ks2, bk, E[c], c);
            pa = min(pa, p);
            if (c <= mx) pcu = min(pcu, p);
        }
        int sm = (int)((constraint ? pa : pcu) & 15u);
        samp[i] = sm;
        constraint |= (sm != mx);
    }

    const int n1 = samp[0] * 1000 + samp[1] * 100 + samp[2] * 10 + samp[3];
    const int n2 = ssv - n1;   // in [0, 10000)

    const int lin = b * NS + sidx;
    g_n1sum[lin] = n1;

    // Output layout (float32 concat): n1_samples[B,S,D,1] | n2d[B,S,D,1] | weights[B,S]
    float4* out_n1 = (float4*)out;
    float4* out_n2 = (float4*)(out + (size_t)NBATCH * NS * ND);
    out_n1[lin] = make_float4((float)samp[0], (float)samp[1],
                              (float)samp[2], (float)samp[3]);
    // sorted-shift trick == plain decimal digits of n2
    out_n2[lin] = make_float4((float)(n2 / 1000), (float)((n2 / 100) % 10),
                              (float)((n2 / 10) % 10), (float)(n2 % 10));
}

// ---------------------------------------------------------------------------
// Per-row histogram (10^4 bins in smem) + gather -> weights.
// Loads prefetched before the atomic burst (MLP), 512 threads.
// ---------------------------------------------------------------------------
__global__ void __launch_bounds__(512)
hist_kernel(float* __restrict__ w) {
    __shared__ int h[10000];
    const int b = blockIdx.x;
    int4* h4 = (int4*)h;
    for (int i = threadIdx.x; i < 2500; i += 512)
        h4[i] = make_int4(0, 0, 0, 0);
    __syncthreads();
    int v[NS / 512];
#pragma unroll
    for (int j = 0; j < NS / 512; j++)
        v[j] = g_n1sum[b * NS + threadIdx.x + j * 512];
#pragma unroll
    for (int j = 0; j < NS / 512; j++)
        atomicAdd(&h[v[j]], 1);
    __syncthreads();
#pragma unroll
    for (int j = 0; j < NS / 512; j++)
        w[b * NS + threadIdx.x + j * 512] = (float)h[v[j]];
}

// ---------------------------------------------------------------------------
// Host: key derivation (threefry on CPU, deterministic, no device work)
// ---------------------------------------------------------------------------
static inline uint32_t h_rotl(uint32_t x, int r) {
    return (x << r) | (x >> (32 - r));
}
static void tf2x32_h(uint32_t k0, uint32_t k1, uint32_t c0, uint32_t c1,
                     uint32_t* o0, uint32_t* o1) {
    uint32_t ks2 = 0x1BD11BDAu ^ k0 ^ k1;
    uint32_t x0 = c0 + k0, x1 = c1 + k1;
#define TFH(r) { x0 += x1; x1 = h_rotl(x1, (r)); x1 ^= x0; }
    TFH(13) TFH(15) TFH(26) TFH(6)
    x0 += k1;  x1 += ks2 + 1u;
    TFH(17) TFH(29) TFH(16) TFH(24)
    x0 += ks2; x1 += k0 + 2u;
    TFH(13) TFH(15) TFH(26) TFH(6)
    x0 += k0;  x1 += k1 + 3u;
    TFH(17) TFH(29) TFH(16) TFH(24)
    x0 += k1;  x1 += ks2 + 4u;
    TFH(13) TFH(15) TFH(26) TFH(6)
    x0 += ks2; x1 += k0 + 5u;
#undef TFH
    *o0 = x0; *o1 = x1;
}

extern "C" void kernel_launch(void* const* d_in, const int* in_sizes, int n_in,
                              void* d_out, int out_size) {
    const float* n1_logits = (const float*)d_in[0];
    const float* counters  = (const float*)d_in[1];
    const int*   s_arr     = (const int*)d_in[2];
    float* out = (float*)d_out;

    // jax.random.key(42) -> (0, 42); 4x split (partitionable mode);
    // categorical uses the sub key.
    uint32_t kk0 = 0u, kk1 = 42u;
    uint32_t keys[8];
    for (int i = 0; i < ND; i++) {
        uint32_t nk0, nk1, sk0, sk1;
        tf2x32_h(kk0, kk1, 0u, 0u, &nk0, &nk1);
        tf2x32_h(kk0, kk1, 0u, 1u, &sk0, &sk1);
        keys[2 * i]     = sk0;
        keys[2 * i + 1] = sk1;
        kk0 = nk0; kk1 = nk1;
    }
    uint4 ka = make_uint4(keys[0], keys[1], keys[2], keys[3]);
    uint4 kb = make_uint4(keys[4], keys[5], keys[6], keys[7]);

    dim3 grid(NS / 256, NBATCH);
    sampler_kernel<<<grid, 256>>>(n1_logits, counters, s_arr, out, ka, kb);

    float* w = out + (size_t)2 * NBATCH * NS * ND;
    hist_kernel<<<NBATCH, 512>>>(w);
}